// round 2
// baseline (speedup 1.0000x reference)
#include <cuda_runtime.h>
#include <math.h>

// Scratch for precomputed pair-group coefficients.
// Layout: A[(g*4+p)*N + row], g in [0,8), p in [0,4).
#define MAXROWS 4096
__device__ float g_A[32 * MAXROWS];
__device__ float g_B[32 * MAXROWS];

typedef unsigned long long ull;

// Packed f32x2 helpers (Blackwell sm_100+).
#define MUL_F32X2(out, a, b) \
    asm("mul.rn.f32x2 %0, %1, %2;" : "=l"(out) : "l"(a), "l"(b))
#define FMA_F32X2(acc, a, b) \
    asm("fma.rn.f32x2 %0, %1, %2, %0;" : "+l"(acc) : "l"(a), "l"(b))
#define DUP_F32X2(out, v) \
    asm("mov.b64 %0, {%1, %1};" : "=l"(out) : "f"(v))
#define ABS_F32X2(out, a) \
    asm("and.b64 %0, %1, %2;" : "=l"(out) : "l"(a), "l"(0x7FFFFFFF7FFFFFFFULL))

// ---------------------------------------------------------------------------
// Precompute: for each row r and wire-pair g (wires 2g, 2g+1):
//   coeffs = (c0*c1, c0*s1, s0*c1, s0*s1), c = cos(x/2), s = sin(x/2).
// Then cos((x0-y0)/2)*cos((x1-y1)/2) = dot4(A[i][g], B[j][g]).
// ---------------------------------------------------------------------------
__global__ void qk_precompute(const float* __restrict__ x,
                              const float* __restrict__ y,
                              int n, int m, int d) {
    int tid = blockIdx.x * blockDim.x + threadIdx.x;
    int total = (n + m) * 8;
    if (tid >= total) return;
    int g = tid & 7;
    int r = tid >> 3;
    const float* src;
    float* dst;
    int N;
    if (r < n) {
        src = x + (size_t)r * d;
        dst = g_A;
        N = n;
    } else {
        r -= n;
        src = y + (size_t)r * d;
        dst = g_B;
        N = m;
    }
    float s0, c0, s1, c1;
    sincosf(0.5f * src[2 * g],     &s0, &c0);
    sincosf(0.5f * src[2 * g + 1], &s1, &c1);
    dst[(g * 4 + 0) * N + r] = c0 * c1;
    dst[(g * 4 + 1) * N + r] = c0 * s1;
    dst[(g * 4 + 2) * N + r] = s0 * c1;
    dst[(g * 4 + 3) * N + r] = s0 * s1;
}

// ---------------------------------------------------------------------------
// Main product kernel: 128x128 tile, 256 threads, 8x8 per thread, f32x2 packed
// over the j dimension. out[i,j] = | prod_g dot4(A[i][g], B[j][g]) |
// ---------------------------------------------------------------------------
__global__ __launch_bounds__(256, 1)
void qk_prod(float* __restrict__ out, int n, int m) {
    __shared__ float As[32][128];  // [g*4+p][i_local]
    __shared__ float Bs[32][128];  // [g*4+p][j_local]

    const int i_base = blockIdx.y * 128;
    const int j_base = blockIdx.x * 128;
    const int tid = threadIdx.x;

    // Fill smem: 32 slices x 128 floats each (1024 float4 per array).
    #pragma unroll
    for (int idx = tid; idx < 1024; idx += 256) {
        int slice = idx >> 5;            // 0..31
        int pos = (idx & 31) << 2;       // 0,4,...,124
        *(float4*)&As[slice][pos] =
            *(const float4*)&g_A[(size_t)slice * n + i_base + pos];
        *(float4*)&Bs[slice][pos] =
            *(const float4*)&g_B[(size_t)slice * m + j_base + pos];
    }
    __syncthreads();

    const int tx = tid & 15;       // j direction (16 x 8 = 128)
    const int ty = tid >> 4;       // i direction (16 x 8 = 128)
    const int i0 = ty * 8;
    const int j0 = tx * 8;

    ull prod[2][4][4];             // [i-half][ii][jpair]

    // ---- g = 0: initialize prod ----
    {
        ull bq[4][4];
        #pragma unroll
        for (int p = 0; p < 4; p++) {
            ulonglong2 b0 = *(const ulonglong2*)&Bs[p][j0];
            ulonglong2 b1 = *(const ulonglong2*)&Bs[p][j0 + 4];
            bq[p][0] = b0.x; bq[p][1] = b0.y; bq[p][2] = b1.x; bq[p][3] = b1.y;
        }
        #pragma unroll
        for (int h = 0; h < 2; h++) {
            ull ad[4][4];
            #pragma unroll
            for (int p = 0; p < 4; p++) {
                float4 av = *(const float4*)&As[p][i0 + h * 4];
                DUP_F32X2(ad[p][0], av.x);
                DUP_F32X2(ad[p][1], av.y);
                DUP_F32X2(ad[p][2], av.z);
                DUP_F32X2(ad[p][3], av.w);
            }
            #pragma unroll
            for (int ii = 0; ii < 4; ii++)
                #pragma unroll
                for (int q = 0; q < 4; q++) {
                    ull t;
                    MUL_F32X2(t, ad[0][ii], bq[0][q]);
                    FMA_F32X2(t, ad[1][ii], bq[1][q]);
                    FMA_F32X2(t, ad[2][ii], bq[2][q]);
                    FMA_F32X2(t, ad[3][ii], bq[3][q]);
                    prod[h][ii][q] = t;
                }
        }
    }

    // ---- g = 1..7: multiply in ----
    #pragma unroll 1
    for (int g = 1; g < 8; g++) {
        ull bq[4][4];
        #pragma unroll
        for (int p = 0; p < 4; p++) {
            ulonglong2 b0 = *(const ulonglong2*)&Bs[g * 4 + p][j0];
            ulonglong2 b1 = *(const ulonglong2*)&Bs[g * 4 + p][j0 + 4];
            bq[p][0] = b0.x; bq[p][1] = b0.y; bq[p][2] = b1.x; bq[p][3] = b1.y;
        }
        #pragma unroll
        for (int h = 0; h < 2; h++) {
            ull ad[4][4];
            #pragma unroll
            for (int p = 0; p < 4; p++) {
                float4 av = *(const float4*)&As[g * 4 + p][i0 + h * 4];
                DUP_F32X2(ad[p][0], av.x);
                DUP_F32X2(ad[p][1], av.y);
                DUP_F32X2(ad[p][2], av.z);
                DUP_F32X2(ad[p][3], av.w);
            }
            #pragma unroll
            for (int ii = 0; ii < 4; ii++)
                #pragma unroll
                for (int q = 0; q < 4; q++) {
                    ull t;
                    MUL_F32X2(t, ad[0][ii], bq[0][q]);
                    FMA_F32X2(t, ad[1][ii], bq[1][q]);
                    FMA_F32X2(t, ad[2][ii], bq[2][q]);
                    FMA_F32X2(t, ad[3][ii], bq[3][q]);
                    MUL_F32X2(prod[h][ii][q], prod[h][ii][q], t);
                }
        }
    }

    // ---- epilogue: abs + store (STG.128 via ulonglong2) ----
    #pragma unroll
    for (int h = 0; h < 2; h++)
        #pragma unroll
        for (int ii = 0; ii < 4; ii++) {
            int row = i_base + i0 + h * 4 + ii;
            ull v0, v1, v2, v3;
            ABS_F32X2(v0, prod[h][ii][0]);
            ABS_F32X2(v1, prod[h][ii][1]);
            ABS_F32X2(v2, prod[h][ii][2]);
            ABS_F32X2(v3, prod[h][ii][3]);
            ulonglong2* dst = (ulonglong2*)&out[(size_t)row * m + j_base + j0];
            dst[0] = make_ulonglong2(v0, v1);
            dst[1] = make_ulonglong2(v2, v3);
        }
}

// ---------------------------------------------------------------------------
// Generic fallback (shape-robust, slow): one thread per output.
// ---------------------------------------------------------------------------
__global__ void qk_generic(const float* __restrict__ x, const float* __restrict__ y,
                           float* __restrict__ out, int n, int m, int d) {
    long long idx = (long long)blockIdx.x * blockDim.x + threadIdx.x;
    long long total = (long long)n * m;
    if (idx >= total) return;
    int i = (int)(idx / m);
    int j = (int)(idx % m);
    float prod = 1.0f;
    for (int k = 0; k < d; k++)
        prod *= cosf(0.5f * (x[(size_t)i * d + k] - y[(size_t)j * d + k]));
    out[idx] = fabsf(prod);
}

extern "C" void kernel_launch(void* const* d_in, const int* in_sizes, int n_in,
                              void* d_out, int out_size) {
    const float* x = (const float*)d_in[0];
    const float* y = (const float*)d_in[1];
    float* out = (float*)d_out;

    // Recover (n, m, d): in_sizes = {n*d, m*d}, out_size = n*m.
    double dd = sqrt((double)in_sizes[0] * (double)in_sizes[1] / (double)out_size);
    int d = (int)(dd + 0.5);
    if (d <= 0) d = 16;
    int n = in_sizes[0] / d;
    int m = in_sizes[1] / d;

    bool fast = (d == 16) && (n % 128 == 0) && (m % 128 == 0) &&
                (n <= MAXROWS) && (m <= MAXROWS) &&
                ((long long)n * d == in_sizes[0]) &&
                ((long long)m * d == in_sizes[1]) &&
                ((long long)n * m == out_size);

    if (fast) {
        int total = (n + m) * 8;
        qk_precompute<<<(total + 255) / 256, 256>>>(x, y, n, m, d);
        dim3 grid(m / 128, n / 128);
        qk_prod<<<grid, 256>>>(out, n, m);
    } else {
        long long total = (long long)n * m;
        int blocks = (int)((total + 255) / 256);
        qk_generic<<<blocks, 256>>>(x, y, out, n, m, d);
    }
}

// round 3
// speedup vs baseline: 1.1326x; 1.1326x over previous
#include <cuda_runtime.h>
#include <math.h>

// Scratch for precomputed pair-group coefficients.
// Layout: A[(g*4+p)*N + row], g in [0,8), p in [0,4).
#define MAXROWS 4096
__device__ float g_A[32 * MAXROWS];
__device__ float g_B[32 * MAXROWS];

typedef unsigned long long ull;

// Packed f32x2 helpers (Blackwell sm_100+).
#define MUL_F32X2(out, a, b) \
    asm("mul.rn.f32x2 %0, %1, %2;" : "=l"(out) : "l"(a), "l"(b))
#define FMA_F32X2(acc, a, b) \
    asm("fma.rn.f32x2 %0, %1, %2, %0;" : "+l"(acc) : "l"(a), "l"(b))
#define DUP_F32X2(out, v) \
    asm("mov.b64 %0, {%1, %1};" : "=l"(out) : "f"(v))
#define ABS_F32X2(out, a) \
    asm("and.b64 %0, %1, %2;" : "=l"(out) : "l"(a), "l"(0x7FFFFFFF7FFFFFFFULL))

// ---------------------------------------------------------------------------
// Precompute: for each row r and wire-pair g (wires 2g, 2g+1):
//   coeffs = (c0*c1, c0*s1, s0*c1, s0*s1), c = cos(x/2), s = sin(x/2).
// Then cos((x0-y0)/2)*cos((x1-y1)/2) = dot4(A[i][g], B[j][g]).
// ---------------------------------------------------------------------------
__global__ void qk_precompute(const float* __restrict__ x,
                              const float* __restrict__ y,
                              int n, int m, int d) {
    int tid = blockIdx.x * blockDim.x + threadIdx.x;
    int total = (n + m) * 8;
    if (tid >= total) return;
    int g = tid & 7;
    int r = tid >> 3;
    const float* src;
    float* dst;
    int N;
    if (r < n) {
        src = x + (size_t)r * d;
        dst = g_A;
        N = n;
    } else {
        r -= n;
        src = y + (size_t)r * d;
        dst = g_B;
        N = m;
    }
    float s0, c0, s1, c1;
    sincosf(0.5f * src[2 * g],     &s0, &c0);
    sincosf(0.5f * src[2 * g + 1], &s1, &c1);
    dst[(g * 4 + 0) * N + r] = c0 * c1;
    dst[(g * 4 + 1) * N + r] = c0 * s1;
    dst[(g * 4 + 2) * N + r] = s0 * c1;
    dst[(g * 4 + 3) * N + r] = s0 * s1;
}

// ---------------------------------------------------------------------------
// Main product kernel: 64(i) x 128(j) tile, 128 threads, 8x8 per thread,
// f32x2 packed over j. out[i,j] = | prod_g dot4(A[i][g], B[j][g]) |
// 128-thread CTA keeps regs*threads low enough for 3 CTAs/SM (occupancy).
// ---------------------------------------------------------------------------
__global__ __launch_bounds__(128, 3)
void qk_prod(float* __restrict__ out, int n, int m) {
    __shared__ float As[32][64];   // [g*4+p][i_local]
    __shared__ float Bs[32][128];  // [g*4+p][j_local]

    const int i_base = blockIdx.y * 64;
    const int j_base = blockIdx.x * 128;
    const int tid = threadIdx.x;

    // Fill smem (coalesced float4): As = 512 float4, Bs = 1024 float4.
    #pragma unroll
    for (int idx = tid; idx < 512; idx += 128) {
        int slice = idx >> 4;            // 0..31
        int pos = (idx & 15) << 2;       // 0..60
        *(float4*)&As[slice][pos] =
            *(const float4*)&g_A[(size_t)slice * n + i_base + pos];
    }
    #pragma unroll
    for (int idx = tid; idx < 1024; idx += 128) {
        int slice = idx >> 5;            // 0..31
        int pos = (idx & 31) << 2;       // 0..124
        *(float4*)&Bs[slice][pos] =
            *(const float4*)&g_B[(size_t)slice * m + j_base + pos];
    }
    __syncthreads();

    const int tx = tid & 15;       // j direction (16 threads x 8 = 128)
    const int ty = tid >> 4;       // i direction (8 threads x 8 = 64)
    const int i0 = ty * 8;
    const int j0 = tx * 8;

    ull prod[2][4][4];             // [i-half][ii][jpair]

    // ---- g = 0: initialize prod ----
    {
        ull bq[4][4];
        #pragma unroll
        for (int p = 0; p < 4; p++) {
            ulonglong2 b0 = *(const ulonglong2*)&Bs[p][j0];
            ulonglong2 b1 = *(const ulonglong2*)&Bs[p][j0 + 4];
            bq[p][0] = b0.x; bq[p][1] = b0.y; bq[p][2] = b1.x; bq[p][3] = b1.y;
        }
        #pragma unroll
        for (int h = 0; h < 2; h++) {
            ull ad[4][4];
            #pragma unroll
            for (int p = 0; p < 4; p++) {
                float4 av = *(const float4*)&As[p][i0 + h * 4];
                DUP_F32X2(ad[p][0], av.x);
                DUP_F32X2(ad[p][1], av.y);
                DUP_F32X2(ad[p][2], av.z);
                DUP_F32X2(ad[p][3], av.w);
            }
            #pragma unroll
            for (int ii = 0; ii < 4; ii++)
                #pragma unroll
                for (int q = 0; q < 4; q++) {
                    ull t;
                    MUL_F32X2(t, ad[0][ii], bq[0][q]);
                    FMA_F32X2(t, ad[1][ii], bq[1][q]);
                    FMA_F32X2(t, ad[2][ii], bq[2][q]);
                    FMA_F32X2(t, ad[3][ii], bq[3][q]);
                    prod[h][ii][q] = t;
                }
        }
    }

    // ---- g = 1..7: multiply in ----
    #pragma unroll 1
    for (int g = 1; g < 8; g++) {
        ull bq[4][4];
        #pragma unroll
        for (int p = 0; p < 4; p++) {
            ulonglong2 b0 = *(const ulonglong2*)&Bs[g * 4 + p][j0];
            ulonglong2 b1 = *(const ulonglong2*)&Bs[g * 4 + p][j0 + 4];
            bq[p][0] = b0.x; bq[p][1] = b0.y; bq[p][2] = b1.x; bq[p][3] = b1.y;
        }
        #pragma unroll
        for (int h = 0; h < 2; h++) {
            ull ad[4][4];
            #pragma unroll
            for (int p = 0; p < 4; p++) {
                float4 av = *(const float4*)&As[g * 4 + p][i0 + h * 4];
                DUP_F32X2(ad[p][0], av.x);
                DUP_F32X2(ad[p][1], av.y);
                DUP_F32X2(ad[p][2], av.z);
                DUP_F32X2(ad[p][3], av.w);
            }
            #pragma unroll
            for (int ii = 0; ii < 4; ii++)
                #pragma unroll
                for (int q = 0; q < 4; q++) {
                    ull t;
                    MUL_F32X2(t, ad[0][ii], bq[0][q]);
                    FMA_F32X2(t, ad[1][ii], bq[1][q]);
                    FMA_F32X2(t, ad[2][ii], bq[2][q]);
                    FMA_F32X2(t, ad[3][ii], bq[3][q]);
                    MUL_F32X2(prod[h][ii][q], prod[h][ii][q], t);
                }
        }
    }

    // ---- epilogue: abs + store (STG.128 via ulonglong2) ----
    #pragma unroll
    for (int h = 0; h < 2; h++)
        #pragma unroll
        for (int ii = 0; ii < 4; ii++) {
            int row = i_base + i0 + h * 4 + ii;
            ull v0, v1, v2, v3;
            ABS_F32X2(v0, prod[h][ii][0]);
            ABS_F32X2(v1, prod[h][ii][1]);
            ABS_F32X2(v2, prod[h][ii][2]);
            ABS_F32X2(v3, prod[h][ii][3]);
            ulonglong2* dst = (ulonglong2*)&out[(size_t)row * m + j_base + j0];
            dst[0] = make_ulonglong2(v0, v1);
            dst[1] = make_ulonglong2(v2, v3);
        }
}

// ---------------------------------------------------------------------------
// Generic fallback (shape-robust, slow): one thread per output.
// ---------------------------------------------------------------------------
__global__ void qk_generic(const float* __restrict__ x, const float* __restrict__ y,
                           float* __restrict__ out, int n, int m, int d) {
    long long idx = (long long)blockIdx.x * blockDim.x + threadIdx.x;
    long long total = (long long)n * m;
    if (idx >= total) return;
    int i = (int)(idx / m);
    int j = (int)(idx % m);
    float prod = 1.0f;
    for (int k = 0; k < d; k++)
        prod *= cosf(0.5f * (x[(size_t)i * d + k] - y[(size_t)j * d + k]));
    out[idx] = fabsf(prod);
}

extern "C" void kernel_launch(void* const* d_in, const int* in_sizes, int n_in,
                              void* d_out, int out_size) {
    const float* x = (const float*)d_in[0];
    const float* y = (const float*)d_in[1];
    float* out = (float*)d_out;

    // Recover (n, m, d): in_sizes = {n*d, m*d}, out_size = n*m.
    double dd = sqrt((double)in_sizes[0] * (double)in_sizes[1] / (double)out_size);
    int d = (int)(dd + 0.5);
    if (d <= 0) d = 16;
    int n = in_sizes[0] / d;
    int m = in_sizes[1] / d;

    bool fast = (d == 16) && (n % 64 == 0) && (m % 128 == 0) &&
                (n <= MAXROWS) && (m <= MAXROWS) &&
                ((long long)n * d == in_sizes[0]) &&
                ((long long)m * d == in_sizes[1]) &&
                ((long long)n * m == out_size);

    if (fast) {
        int total = (n + m) * 8;
        qk_precompute<<<(total + 255) / 256, 256>>>(x, y, n, m, d);
        dim3 grid(m / 128, n / 64);
        qk_prod<<<grid, 128>>>(out, n, m);
    } else {
        long long total = (long long)n * m;
        int blocks = (int)((total + 255) / 256);
        qk_generic<<<blocks, 256>>>(x, y, out, n, m, d);
    }
}